// round 4
// baseline (speedup 1.0000x reference)
#include <cuda_runtime.h>
#include <math.h>

#define MROWS 4096
#define DMODEL 1024
#define QPROJ 512
#define KVPROJ 1024
#define NH 16
#define DH 64
#define SEQ 2048
#define BATCH 2
#define EPS 1e-5f

// ---------------- scratch (no allocations allowed) ----------------
__device__ float g_xq  [MROWS * DMODEL];
__device__ float g_xkv [MROWS * DMODEL];
__device__ float g_tq  [MROWS * QPROJ];
__device__ float g_cq  [MROWS * QPROJ];
__device__ float g_Q   [MROWS * DMODEL];
__device__ float g_tkv [MROWS * KVPROJ];
__device__ float g_ckv [MROWS * KVPROJ];
__device__ float g_KV  [MROWS * 2 * DMODEL];
__device__ float g_attn[MROWS * DMODEL];

// ---------------- tf32 / async helpers ----------------
__device__ __forceinline__ unsigned f2tf(float f) {
    unsigned u; asm("cvt.rna.tf32.f32 %0, %1;" : "=r"(u) : "f"(f)); return u;
}
__device__ __forceinline__ uint4 cvt4(float4 v) {
    uint4 u; u.x = f2tf(v.x); u.y = f2tf(v.y); u.z = f2tf(v.z); u.w = f2tf(v.w); return u;
}
__device__ __forceinline__ void mma_tf32(float c[4], unsigned a0, unsigned a1, unsigned a2, unsigned a3,
                                         unsigned b0, unsigned b1) {
    asm volatile(
        "mma.sync.aligned.m16n8k8.row.col.f32.tf32.tf32.f32 "
        "{%0,%1,%2,%3},{%4,%5,%6,%7},{%8,%9},{%0,%1,%2,%3};"
        : "+f"(c[0]), "+f"(c[1]), "+f"(c[2]), "+f"(c[3])
        : "r"(a0), "r"(a1), "r"(a2), "r"(a3), "r"(b0), "r"(b1));
}
__device__ __forceinline__ void cp16(unsigned dst, const void* src) {
    asm volatile("cp.async.cg.shared.global [%0], [%1], 16;" :: "r"(dst), "l"(src));
}
__device__ __forceinline__ void cp_commit() { asm volatile("cp.async.commit_group;"); }
template <int N>
__device__ __forceinline__ void cp_wait() { asm volatile("cp.async.wait_group %0;" :: "n"(N)); }

// ---------------- block reduction (sum, sumsq), 256 threads ----------------
__device__ __forceinline__ float2 block_reduce2(float s, float q, float* sh) {
    #pragma unroll
    for (int o = 16; o; o >>= 1) {
        s += __shfl_xor_sync(0xffffffffu, s, o);
        q += __shfl_xor_sync(0xffffffffu, q, o);
    }
    int w = threadIdx.x >> 5;
    if ((threadIdx.x & 31) == 0) { sh[w] = s; sh[8 + w] = q; }
    __syncthreads();
    if (threadIdx.x < 32) {
        s = (threadIdx.x < 8) ? sh[threadIdx.x] : 0.f;
        q = (threadIdx.x < 8) ? sh[8 + threadIdx.x] : 0.f;
        #pragma unroll
        for (int o = 4; o; o >>= 1) {
            s += __shfl_xor_sync(0xffffffffu, s, o);
            q += __shfl_xor_sync(0xffffffffu, q, o);
        }
        if (threadIdx.x == 0) { sh[16] = s; sh[17] = q; }
    }
    __syncthreads();
    return make_float2(sh[16], sh[17]);
}

// ---------------- fused dual pre-LN ----------
__global__ void __launch_bounds__(256) prenorm_kernel(
    const float* __restrict__ x,
    const float* __restrict__ pg, const float* __restrict__ pb,
    const float* __restrict__ kg, const float* __restrict__ kb,
    float* __restrict__ xq, float* __restrict__ xkv)
{
    __shared__ float sh[18];
    int row = blockIdx.x;
    const float* xr = x + (size_t)row * DMODEL;
    float s = 0.f, q = 0.f;
    #pragma unroll
    for (int i = threadIdx.x; i < DMODEL; i += 256) { float v = xr[i]; s += v; q += v * v; }
    float2 r = block_reduce2(s, q, sh);
    float mu = r.x * (1.f / DMODEL);
    float var = r.y * (1.f / DMODEL) - mu * mu;
    float inv = rsqrtf(var + EPS);
    #pragma unroll
    for (int i = threadIdx.x; i < DMODEL; i += 256) {
        float n = (xr[i] - mu) * inv;
        xq [(size_t)row * DMODEL + i] = n * pg[i] + pb[i];
        xkv[(size_t)row * DMODEL + i] = n * kg[i] + kb[i];
    }
}

// ---------------- generic row LN ----------------
__global__ void __launch_bounds__(256) ln_kernel(
    const float* __restrict__ x, const float* __restrict__ g,
    const float* __restrict__ b, float* __restrict__ y, int N)
{
    __shared__ float sh[18];
    int row = blockIdx.x;
    const float* xr = x + (size_t)row * N;
    float s = 0.f, q = 0.f;
    for (int i = threadIdx.x; i < N; i += 256) { float v = xr[i]; s += v; q += v * v; }
    float2 r = block_reduce2(s, q, sh);
    float mu = r.x / N;
    float var = r.y / N - mu * mu;
    float inv = rsqrtf(var + EPS);
    for (int i = threadIdx.x; i < N; i += 256)
        y[(size_t)row * N + i] = (xr[i] - mu) * inv * g[i] + b[i];
}

// ---------------- tf32 tensor-core GEMM (unchanged) -----------------
#define GBM 128
#define GBN 128
#define GBK 32
#define ASTRIDE 516
#define BSTRIDE 136

template <bool TB>
__global__ void __launch_bounds__(256) gemm_tf32(
    const float* __restrict__ A, const float* __restrict__ B,
    float* __restrict__ C, int N, int K, float alpha)
{
    __shared__ unsigned As[8 * ASTRIDE];
    __shared__ unsigned Bs[GBK * BSTRIDE];

    int tid = threadIdx.x;
    int m0 = blockIdx.y * GBM, n0 = blockIdx.x * GBN;
    int warp = tid >> 5, lane = tid & 31;
    int g = lane >> 2, t = lane & 3;
    int wm = (warp & 1) * 64, wn = (warp >> 1) * 32;

    int ar = tid >> 3, ac4 = tid & 7;
    int br = tid >> 5, bc4 = tid & 31;
    int tn = tid >> 3, tk4 = tid & 7;

    float4 ra[4], rb[4];

    auto loadT = [&](int k0) {
        #pragma unroll
        for (int i = 0; i < 4; i++)
            ra[i] = *(const float4*)&A[(size_t)(m0 + ar + 32 * i) * K + k0 + ac4 * 4];
        if (!TB) {
            #pragma unroll
            for (int i = 0; i < 4; i++)
                rb[i] = *(const float4*)&B[(size_t)(k0 + br + 8 * i) * N + n0 + bc4 * 4];
        } else {
            #pragma unroll
            for (int i = 0; i < 4; i++)
                rb[i] = *(const float4*)&B[(size_t)(n0 + tn + 32 * i) * K + k0 + tk4 * 4];
        }
    };
    auto storeT = [&]() {
        #pragma unroll
        for (int i = 0; i < 4; i++)
            *(uint4*)&As[ac4 * ASTRIDE + (ar + 32 * i) * 4] = cvt4(ra[i]);
        if (!TB) {
            #pragma unroll
            for (int i = 0; i < 4; i++)
                *(uint4*)&Bs[(br + 8 * i) * BSTRIDE + bc4 * 4] = cvt4(rb[i]);
        } else {
            #pragma unroll
            for (int i = 0; i < 4; i++) {
                int n = tn + 32 * i;
                Bs[(tk4 * 4 + 0) * BSTRIDE + n] = f2tf(rb[i].x);
                Bs[(tk4 * 4 + 1) * BSTRIDE + n] = f2tf(rb[i].y);
                Bs[(tk4 * 4 + 2) * BSTRIDE + n] = f2tf(rb[i].z);
                Bs[(tk4 * 4 + 3) * BSTRIDE + n] = f2tf(rb[i].w);
            }
        }
    };

    float c[4][4][4] = {};

    loadT(0);
    storeT();
    __syncthreads();

    for (int k0 = GBK; ; k0 += GBK) {
        bool more = k0 < K;
        if (more) loadT(k0);

        #pragma unroll
        for (int ks = 0; ks < GBK; ks += 8) {
            unsigned bf[4][2];
            #pragma unroll
            for (int nf = 0; nf < 4; nf++) {
                bf[nf][0] = Bs[(ks + t) * BSTRIDE + wn + nf * 8 + g];
                bf[nf][1] = Bs[(ks + t + 4) * BSTRIDE + wn + nf * 8 + g];
            }
            #pragma unroll
            for (int mf = 0; mf < 4; mf++) {
                int mb = wm + mf * 16 + g;
                int grp = ks >> 2;
                unsigned a0 = As[grp * ASTRIDE + mb * 4 + t];
                unsigned a1 = As[grp * ASTRIDE + (mb + 8) * 4 + t];
                unsigned a2 = As[(grp + 1) * ASTRIDE + mb * 4 + t];
                unsigned a3 = As[(grp + 1) * ASTRIDE + (mb + 8) * 4 + t];
                #pragma unroll
                for (int nf = 0; nf < 4; nf++)
                    mma_tf32(c[mf][nf], a0, a1, a2, a3, bf[nf][0], bf[nf][1]);
            }
        }
        if (!more) break;
        __syncthreads();
        storeT();
        __syncthreads();
    }

    #pragma unroll
    for (int mf = 0; mf < 4; mf++) {
        int r0 = m0 + wm + mf * 16 + g;
        #pragma unroll
        for (int nf = 0; nf < 4; nf++) {
            int cc = n0 + wn + nf * 8 + 2 * t;
            float2 lo = make_float2(alpha * c[mf][nf][0], alpha * c[mf][nf][1]);
            float2 hi = make_float2(alpha * c[mf][nf][2], alpha * c[mf][nf][3]);
            *(float2*)&C[(size_t)r0 * N + cc] = lo;
            *(float2*)&C[(size_t)(r0 + 8) * N + cc] = hi;
        }
    }
}

// ---------------- tensor-core causal flash attention, v2 --------------------
// 256 threads (8 warps), 128-query tile; warp w owns rows w*16..w*16+15.
// K/V chunks (64 keys) double-buffered via cp.async. Strides: QP 68, KV 76
// (both conflict-free for their access patterns).
#define AQ_ROWS 128
#define QP_STR 68
#define KV_STR 76
#define ATT_SMEM ((AQ_ROWS * QP_STR + 4 * 64 * KV_STR) * 4)

extern __shared__ float att_sm[];

__global__ void __launch_bounds__(256) attn_tc_kernel(
    const float* __restrict__ Q, const float* __restrict__ KV, float* __restrict__ O)
{
    float* sQP = att_sm;                         // 128*68
    float* sKV[2][2];                            // [buf][K=0/V=1]
    sKV[0][0] = sQP + AQ_ROWS * QP_STR;
    sKV[0][1] = sKV[0][0] + 64 * KV_STR;
    sKV[1][0] = sKV[0][1] + 64 * KV_STR;
    sKV[1][1] = sKV[1][0] + 64 * KV_STR;

    int tid = threadIdx.x, warp = tid >> 5, lane = tid & 31;
    int g = lane >> 2, t = lane & 3;
    int wm = warp * 16;
    int qt = (int)gridDim.x - 1 - (int)blockIdx.x;   // heavy tiles first
    int h = blockIdx.y, b = blockIdx.z;
    int qrow0 = qt * AQ_ROWS;
    int nch = 2 * qt + 2;

    // ---- load Q tile -> smem ----
    #pragma unroll
    for (int it = 0; it < 8; it++) {
        int idx = tid + it * 256;
        int r = idx >> 4, c4 = idx & 15;
        float4 v = *(const float4*)&Q[((size_t)(b * SEQ + qrow0 + r)) * DMODEL + h * DH + c4 * 4];
        *(float4*)&sQP[r * QP_STR + c4 * 4] = v;
    }
    __syncthreads();

    // ---- Q A-fragments in registers (raw fp32 bits -> tf32 truncation) ----
    unsigned qa[8][4];
    #pragma unroll
    for (int ks = 0; ks < 8; ks++) {
        qa[ks][0] = __float_as_uint(sQP[(wm + g)     * QP_STR + ks * 8 + t]);
        qa[ks][1] = __float_as_uint(sQP[(wm + g + 8) * QP_STR + ks * 8 + t]);
        qa[ks][2] = __float_as_uint(sQP[(wm + g)     * QP_STR + ks * 8 + t + 4]);
        qa[ks][3] = __float_as_uint(sQP[(wm + g + 8) * QP_STR + ks * 8 + t + 4]);
    }
    __syncthreads();   // QP buffer now free for P

    // cp.async loader: one chunk (64 keys) of K and V into buffer bf
    int lr = tid >> 4, lc4 = tid & 15;   // 256 threads: 16 rows x 16 col4 per pass
    auto loadKV = [&](int ch, int bf) {
        const float* src = &KV[((size_t)(b * SEQ + ch * 64 + lr)) * (2 * DMODEL) + h * DH + lc4 * 4];
        unsigned dK = (unsigned)__cvta_generic_to_shared(&sKV[bf][0][lr * KV_STR + lc4 * 4]);
        unsigned dV = (unsigned)__cvta_generic_to_shared(&sKV[bf][1][lr * KV_STR + lc4 * 4]);
        #pragma unroll
        for (int it = 0; it < 4; it++) {
            cp16(dK + it * 16 * KV_STR * 4, src + (size_t)it * 16 * (2 * DMODEL));
            cp16(dV + it * 16 * KV_STR * 4, src + (size_t)it * 16 * (2 * DMODEL) + DMODEL);
        }
        cp_commit();
    };

    float m0 = -INFINITY, m1 = -INFINITY, l0 = 0.f, l1 = 0.f;
    float co[8][4] = {};

    loadKV(0, 0);

    for (int ch = 0; ch < nch; ch++) {
        int cur = ch & 1;
        if (ch + 1 < nch) { loadKV(ch + 1, cur ^ 1); cp_wait<1>(); }
        else              { cp_wait<0>(); }
        __syncthreads();

        const float* cK = sKV[cur][0];
        const float* cV = sKV[cur][1];

        // ---- S = Q K^T ----
        float s[8][4] = {};
        #pragma unroll
        for (int ks = 0; ks < 8; ks++) {
            #pragma unroll
            for (int nf = 0; nf < 8; nf++) {
                unsigned b0 = __float_as_uint(cK[(nf * 8 + g) * KV_STR + ks * 8 + t]);
                unsigned b1 = __float_as_uint(cK[(nf * 8 + g) * KV_STR + ks * 8 + t + 4]);
                mma_tf32(s[nf], qa[ks][0], qa[ks][1], qa[ks][2], qa[ks][3], b0, b1);
            }
        }

        // ---- causal mask (only last two chunks can touch the diagonal) ----
        if (ch >= 2 * qt) {
            int r0 = qrow0 + wm + g, r1 = r0 + 8;
            #pragma unroll
            for (int nf = 0; nf < 8; nf++) {
                int col = ch * 64 + nf * 8 + 2 * t;
                if (col     > r0) s[nf][0] = -1e30f;
                if (col + 1 > r0) s[nf][1] = -1e30f;
                if (col     > r1) s[nf][2] = -1e30f;
                if (col + 1 > r1) s[nf][3] = -1e30f;
            }
        }

        // ---- online softmax (quad-lane reductions) ----
        float mx0 = -1e30f, mx1 = -1e30f;
        #pragma unroll
        for (int nf = 0; nf < 8; nf++) {
            mx0 = fmaxf(mx0, fmaxf(s[nf][0], s[nf][1]));
            mx1 = fmaxf(mx1, fmaxf(s[nf][2], s[nf][3]));
        }
        mx0 = fmaxf(mx0, __shfl_xor_sync(0xffffffffu, mx0, 1));
        mx0 = fmaxf(mx0, __shfl_xor_sync(0xffffffffu, mx0, 2));
        mx1 = fmaxf(mx1, __shfl_xor_sync(0xffffffffu, mx1, 1));
        mx1 = fmaxf(mx1, __shfl_xor_sync(0xffffffffu, mx1, 2));
        float nm0 = fmaxf(m0, mx0), nm1 = fmaxf(m1, mx1);
        float sc0 = __expf(m0 - nm0), sc1 = __expf(m1 - nm1);
        m0 = nm0; m1 = nm1;
        float sum0 = 0.f, sum1 = 0.f;
        #pragma unroll
        for (int nf = 0; nf < 8; nf++) {
            s[nf][0] = __expf(s[nf][0] - m0); sum0 += s[nf][0];
            s[nf][1] = __expf(s[nf][1] - m0); sum0 += s[nf][1];
            s[nf][2] = __expf(s[nf][2] - m1); sum1 += s[nf][2];
            s[nf][3] = __expf(s[nf][3] - m1); sum1 += s[nf][3];
        }
        sum0 += __shfl_xor_sync(0xffffffffu, sum0, 1);
        sum0 += __shfl_xor_sync(0xffffffffu, sum0, 2);
        sum1 += __shfl_xor_sync(0xffffffffu, sum1, 1);
        sum1 += __shfl_xor_sync(0xffffffffu, sum1, 2);
        l0 = l0 * sc0 + sum0;
        l1 = l1 * sc1 + sum1;
        #pragma unroll
        for (int nf = 0; nf < 8; nf++) {
            co[nf][0] *= sc0; co[nf][1] *= sc0;
            co[nf][2] *= sc1; co[nf][3] *= sc1;
        }

        // ---- write P (tf32, rna) to this warp's rows of QP buffer ----
        #pragma unroll
        for (int nf = 0; nf < 8; nf++) {
            int cbase = nf * 8 + 2 * t;
            sQP[(wm + g)     * QP_STR + cbase]     = __uint_as_float(f2tf(s[nf][0]));
            sQP[(wm + g)     * QP_STR + cbase + 1] = __uint_as_float(f2tf(s[nf][1]));
            sQP[(wm + g + 8) * QP_STR + cbase]     = __uint_as_float(f2tf(s[nf][2]));
            sQP[(wm + g + 8) * QP_STR + cbase + 1] = __uint_as_float(f2tf(s[nf][3]));
        }
        __syncwarp();

        // ---- O += P V ----
        #pragma unroll
        for (int ks = 0; ks < 8; ks++) {
            unsigned pa0 = __float_as_uint(sQP[(wm + g)     * QP_STR + ks * 8 + t]);
            unsigned pa1 = __float_as_uint(sQP[(wm + g + 8) * QP_STR + ks * 8 + t]);
            unsigned pa2 = __float_as_uint(sQP[(wm + g)     * QP_STR + ks * 8 + t + 4]);
            unsigned pa3 = __float_as_uint(sQP[(wm + g + 8) * QP_STR + ks * 8 + t + 4]);
            #pragma unroll
            for (int nf = 0; nf < 8; nf++) {
                unsigned b0 = f2tf(cV[(ks * 8 + t)     * KV_STR + nf * 8 + g]);
                unsigned b1 = f2tf(cV[(ks * 8 + t + 4) * KV_STR + nf * 8 + g]);
                mma_tf32(co[nf], pa0, pa1, pa2, pa3, b0, b1);
            }
        }
        __syncthreads();   // all warps done with cur buffer before it is reloaded
    }

    // ---- epilogue ----
    float inv0 = 1.f / l0, inv1 = 1.f / l1;
    size_t row0 = (size_t)(b * SEQ + qrow0 + wm + g) * DMODEL + h * DH;
    size_t row1 = (size_t)(b * SEQ + qrow0 + wm + g + 8) * DMODEL + h * DH;
    #pragma unroll
    for (int nf = 0; nf < 8; nf++) {
        int cbase = nf * 8 + 2 * t;
        *(float2*)&O[row0 + cbase] = make_float2(co[nf][0] * inv0, co[nf][1] * inv0);
        *(float2*)&O[row1 + cbase] = make_float2(co[nf][2] * inv1, co[nf][3] * inv1);
    }
}

// ---------------- launch ----------------
extern "C" void kernel_launch(void* const* d_in, const int* in_sizes, int n_in,
                              void* d_out, int out_size)
{
    const float* x     = (const float*)d_in[0];
    const float* W_dq  = (const float*)d_in[1];
    const float* W_uq  = (const float*)d_in[2];
    const float* q_g   = (const float*)d_in[3];
    const float* q_b   = (const float*)d_in[4];
    const float* W_dkv = (const float*)d_in[5];
    const float* W_ukv = (const float*)d_in[6];
    const float* kv_g  = (const float*)d_in[7];
    const float* kv_b  = (const float*)d_in[8];
    const float* pq_g  = (const float*)d_in[9];
    const float* pq_b  = (const float*)d_in[10];
    const float* pk_g  = (const float*)d_in[11];
    const float* pk_b  = (const float*)d_in[12];
    const float* wo    = (const float*)d_in[13];
    float* out = (float*)d_out;

    float *xq, *xkv, *tq, *cq, *Qp, *tkv, *ckv, *KV, *attn;
    cudaGetSymbolAddress((void**)&xq,   g_xq);
    cudaGetSymbolAddress((void**)&xkv,  g_xkv);
    cudaGetSymbolAddress((void**)&tq,   g_tq);
    cudaGetSymbolAddress((void**)&cq,   g_cq);
    cudaGetSymbolAddress((void**)&Qp,   g_Q);
    cudaGetSymbolAddress((void**)&tkv,  g_tkv);
    cudaGetSymbolAddress((void**)&ckv,  g_ckv);
    cudaGetSymbolAddress((void**)&KV,   g_KV);
    cudaGetSymbolAddress((void**)&attn, g_attn);

    cudaFuncSetAttribute(attn_tc_kernel, cudaFuncAttributeMaxDynamicSharedMemorySize, ATT_SMEM);

    // 1. fused dual pre-LN (shared mean/var)
    prenorm_kernel<<<MROWS, 256>>>(x, pq_g, pq_b, pk_g, pk_b, xq, xkv);
    // 2-4. Q path
    gemm_tf32<false><<<dim3(QPROJ / GBN, MROWS / GBM), 256>>>(xq, W_dq, tq, QPROJ, DMODEL, 1.f);
    ln_kernel<<<MROWS, 256>>>(tq, q_g, q_b, cq, QPROJ);
    gemm_tf32<false><<<dim3(DMODEL / GBN, MROWS / GBM), 256>>>(cq, W_uq, Qp, DMODEL, QPROJ, 0.125f);
    // 5-7. KV path
    gemm_tf32<false><<<dim3(KVPROJ / GBN, MROWS / GBM), 256>>>(xkv, W_dkv, tkv, KVPROJ, DMODEL, 1.f);
    ln_kernel<<<MROWS, 256>>>(tkv, kv_g, kv_b, ckv, KVPROJ);
    gemm_tf32<false><<<dim3(2 * DMODEL / GBN, MROWS / GBM), 256>>>(ckv, W_ukv, KV, 2 * DMODEL, KVPROJ, 1.f);
    // 8. tensor-core causal flash attention (128-row tiles, cp.async pipeline)
    attn_tc_kernel<<<dim3(SEQ / AQ_ROWS, NH, BATCH), 256, ATT_SMEM>>>(Qp, KV, attn);
    // 9. output projection: attn @ wo^T
    gemm_tf32<true><<<dim3(DMODEL / GBN, MROWS / GBM), 256>>>(attn, wo, out, DMODEL, DMODEL, 1.f);
}

// round 5
// speedup vs baseline: 1.0543x; 1.0543x over previous
#include <cuda_runtime.h>
#include <math.h>

#define MROWS 4096
#define DMODEL 1024
#define QPROJ 512
#define KVPROJ 1024
#define NH 16
#define DH 64
#define SEQ 2048
#define BATCH 2
#define EPS 1e-5f
#define LOG2E 1.44269504088896340736f

// ---------------- scratch (no allocations allowed) ----------------
__device__ float g_xq  [MROWS * DMODEL];
__device__ float g_xkv [MROWS * DMODEL];
__device__ float g_tq  [MROWS * QPROJ];
__device__ float g_cq  [MROWS * QPROJ];
__device__ float g_Q   [MROWS * DMODEL];
__device__ float g_tkv [MROWS * KVPROJ];
__device__ float g_ckv [MROWS * KVPROJ];
__device__ float g_KV  [MROWS * 2 * DMODEL];
__device__ float g_attn[MROWS * DMODEL];

// ---------------- tf32 helpers ----------------
__device__ __forceinline__ unsigned f2tf(float f) {
    unsigned u; asm("cvt.rna.tf32.f32 %0, %1;" : "=r"(u) : "f"(f)); return u;
}
__device__ __forceinline__ uint4 cvt4(float4 v) {
    uint4 u; u.x = f2tf(v.x); u.y = f2tf(v.y); u.z = f2tf(v.z); u.w = f2tf(v.w); return u;
}
__device__ __forceinline__ float ex2(float x) {
    float r; asm("ex2.approx.f32 %0, %1;" : "=f"(r) : "f"(x)); return r;
}
__device__ __forceinline__ void mma_tf32(float c[4], unsigned a0, unsigned a1, unsigned a2, unsigned a3,
                                         unsigned b0, unsigned b1) {
    asm volatile(
        "mma.sync.aligned.m16n8k8.row.col.f32.tf32.tf32.f32 "
        "{%0,%1,%2,%3},{%4,%5,%6,%7},{%8,%9},{%0,%1,%2,%3};"
        : "+f"(c[0]), "+f"(c[1]), "+f"(c[2]), "+f"(c[3])
        : "r"(a0), "r"(a1), "r"(a2), "r"(a3), "r"(b0), "r"(b1));
}

// ---------------- block reduction (sum, sumsq), 256 threads ----------------
__device__ __forceinline__ float2 block_reduce2(float s, float q, float* sh) {
    #pragma unroll
    for (int o = 16; o; o >>= 1) {
        s += __shfl_xor_sync(0xffffffffu, s, o);
        q += __shfl_xor_sync(0xffffffffu, q, o);
    }
    int w = threadIdx.x >> 5;
    if ((threadIdx.x & 31) == 0) { sh[w] = s; sh[8 + w] = q; }
    __syncthreads();
    if (threadIdx.x < 32) {
        s = (threadIdx.x < 8) ? sh[threadIdx.x] : 0.f;
        q = (threadIdx.x < 8) ? sh[8 + threadIdx.x] : 0.f;
        #pragma unroll
        for (int o = 4; o; o >>= 1) {
            s += __shfl_xor_sync(0xffffffffu, s, o);
            q += __shfl_xor_sync(0xffffffffu, q, o);
        }
        if (threadIdx.x == 0) { sh[16] = s; sh[17] = q; }
    }
    __syncthreads();
    return make_float2(sh[16], sh[17]);
}

// ---------------- fused dual pre-LN (float4) ----------
__global__ void __launch_bounds__(256) prenorm_kernel(
    const float* __restrict__ x,
    const float* __restrict__ pg, const float* __restrict__ pb,
    const float* __restrict__ kg, const float* __restrict__ kb,
    float* __restrict__ xq, float* __restrict__ xkv)
{
    __shared__ float sh[18];
    int row = blockIdx.x;
    int i = threadIdx.x * 4;           // DMODEL = 1024 = 256*4
    const float* xr = x + (size_t)row * DMODEL;
    float4 v = *(const float4*)&xr[i];
    float s = v.x + v.y + v.z + v.w;
    float q = v.x * v.x + v.y * v.y + v.z * v.z + v.w * v.w;
    float2 r = block_reduce2(s, q, sh);
    float mu = r.x * (1.f / DMODEL);
    float var = r.y * (1.f / DMODEL) - mu * mu;
    float inv = rsqrtf(var + EPS);
    float4 g1 = *(const float4*)&pg[i], b1 = *(const float4*)&pb[i];
    float4 g2 = *(const float4*)&kg[i], b2 = *(const float4*)&kb[i];
    float4 n = make_float4((v.x - mu) * inv, (v.y - mu) * inv, (v.z - mu) * inv, (v.w - mu) * inv);
    *(float4*)&xq [(size_t)row * DMODEL + i] =
        make_float4(n.x * g1.x + b1.x, n.y * g1.y + b1.y, n.z * g1.z + b1.z, n.w * g1.w + b1.w);
    *(float4*)&xkv[(size_t)row * DMODEL + i] =
        make_float4(n.x * g2.x + b2.x, n.y * g2.y + b2.y, n.z * g2.z + b2.z, n.w * g2.w + b2.w);
}

// ---------------- generic row LN (float4) ----------------
__global__ void __launch_bounds__(256) ln_kernel(
    const float* __restrict__ x, const float* __restrict__ g,
    const float* __restrict__ b, float* __restrict__ y, int N)
{
    __shared__ float sh[18];
    int row = blockIdx.x;
    const float* xr = x + (size_t)row * N;
    float s = 0.f, q = 0.f;
    for (int i = threadIdx.x * 4; i < N; i += 1024) {
        float4 v = *(const float4*)&xr[i];
        s += v.x + v.y + v.z + v.w;
        q += v.x * v.x + v.y * v.y + v.z * v.z + v.w * v.w;
    }
    float2 r = block_reduce2(s, q, sh);
    float mu = r.x / N;
    float var = r.y / N - mu * mu;
    float inv = rsqrtf(var + EPS);
    for (int i = threadIdx.x * 4; i < N; i += 1024) {
        float4 v = *(const float4*)&xr[i];
        float4 gv = *(const float4*)&g[i], bv = *(const float4*)&b[i];
        *(float4*)&y[(size_t)row * N + i] = make_float4(
            (v.x - mu) * inv * gv.x + bv.x, (v.y - mu) * inv * gv.y + bv.y,
            (v.z - mu) * inv * gv.z + bv.z, (v.w - mu) * inv * gv.w + bv.w);
    }
}

// ---------------- tf32 tensor-core GEMM -----------------
// ROUND: store outputs tf32-rounded (consumers can use raw bits as exact tf32).
#define GBM 128
#define GBN 128
#define GBK 32
#define ASTRIDE 516
#define BSTRIDE 136

template <bool TB, bool ROUND>
__global__ void __launch_bounds__(256) gemm_tf32(
    const float* __restrict__ A, const float* __restrict__ B,
    float* __restrict__ C, int N, int K, float alpha)
{
    __shared__ unsigned As[8 * ASTRIDE];
    __shared__ unsigned Bs[GBK * BSTRIDE];

    int tid = threadIdx.x;
    int m0 = blockIdx.y * GBM, n0 = blockIdx.x * GBN;
    int warp = tid >> 5, lane = tid & 31;
    int g = lane >> 2, t = lane & 3;
    int wm = (warp & 1) * 64, wn = (warp >> 1) * 32;

    int ar = tid >> 3, ac4 = tid & 7;
    int br = tid >> 5, bc4 = tid & 31;
    int tn = tid >> 3, tk4 = tid & 7;

    float4 ra[4], rb[4];

    auto loadT = [&](int k0) {
        #pragma unroll
        for (int i = 0; i < 4; i++)
            ra[i] = *(const float4*)&A[(size_t)(m0 + ar + 32 * i) * K + k0 + ac4 * 4];
        if (!TB) {
            #pragma unroll
            for (int i = 0; i < 4; i++)
                rb[i] = *(const float4*)&B[(size_t)(k0 + br + 8 * i) * N + n0 + bc4 * 4];
        } else {
            #pragma unroll
            for (int i = 0; i < 4; i++)
                rb[i] = *(const float4*)&B[(size_t)(n0 + tn + 32 * i) * K + k0 + tk4 * 4];
        }
    };
    auto storeT = [&]() {
        #pragma unroll
        for (int i = 0; i < 4; i++)
            *(uint4*)&As[ac4 * ASTRIDE + (ar + 32 * i) * 4] = cvt4(ra[i]);
        if (!TB) {
            #pragma unroll
            for (int i = 0; i < 4; i++)
                *(uint4*)&Bs[(br + 8 * i) * BSTRIDE + bc4 * 4] = cvt4(rb[i]);
        } else {
            #pragma unroll
            for (int i = 0; i < 4; i++) {
                int n = tn + 32 * i;
                Bs[(tk4 * 4 + 0) * BSTRIDE + n] = f2tf(rb[i].x);
                Bs[(tk4 * 4 + 1) * BSTRIDE + n] = f2tf(rb[i].y);
                Bs[(tk4 * 4 + 2) * BSTRIDE + n] = f2tf(rb[i].z);
                Bs[(tk4 * 4 + 3) * BSTRIDE + n] = f2tf(rb[i].w);
            }
        }
    };

    float c[4][4][4] = {};

    loadT(0);
    storeT();
    __syncthreads();

    for (int k0 = GBK; ; k0 += GBK) {
        bool more = k0 < K;
        if (more) loadT(k0);

        #pragma unroll
        for (int ks = 0; ks < GBK; ks += 8) {
            unsigned bf[4][2];
            #pragma unroll
            for (int nf = 0; nf < 4; nf++) {
                bf[nf][0] = Bs[(ks + t) * BSTRIDE + wn + nf * 8 + g];
                bf[nf][1] = Bs[(ks + t + 4) * BSTRIDE + wn + nf * 8 + g];
            }
            #pragma unroll
            for (int mf = 0; mf < 4; mf++) {
                int mb = wm + mf * 16 + g;
                int grp = ks >> 2;
                unsigned a0 = As[grp * ASTRIDE + mb * 4 + t];
                unsigned a1 = As[grp * ASTRIDE + (mb + 8) * 4 + t];
                unsigned a2 = As[(grp + 1) * ASTRIDE + mb * 4 + t];
                unsigned a3 = As[(grp + 1) * ASTRIDE + (mb + 8) * 4 + t];
                #pragma unroll
                for (int nf = 0; nf < 4; nf++)
                    mma_tf32(c[mf][nf], a0, a1, a2, a3, bf[nf][0], bf[nf][1]);
            }
        }
        if (!more) break;
        __syncthreads();
        storeT();
        __syncthreads();
    }

    auto outv = [&](float v) -> float {
        return ROUND ? __uint_as_float(f2tf(alpha * v)) : alpha * v;
    };
    #pragma unroll
    for (int mf = 0; mf < 4; mf++) {
        int r0 = m0 + wm + mf * 16 + g;
        #pragma unroll
        for (int nf = 0; nf < 4; nf++) {
            int cc = n0 + wn + nf * 8 + 2 * t;
            float2 lo = make_float2(outv(c[mf][nf][0]), outv(c[mf][nf][1]));
            float2 hi = make_float2(outv(c[mf][nf][2]), outv(c[mf][nf][3]));
            *(float2*)&C[(size_t)r0 * N + cc] = lo;
            *(float2*)&C[(size_t)(r0 + 8) * N + cc] = hi;
        }
    }
}

// ---------------- tensor-core causal flash attention ------------------------
// 128 threads (4 warps), 64-query tile; warp w owns rows w*16..w*16+15.
// Q, K, V are tf32-pre-rounded by producing GEMMs -> raw bits are exact operands.
// Scores are in log2 domain (Q pre-scaled by 0.125*log2e); softmax uses ex2.
#define QP_STR 68
#define KV_STR 76
#define ATT_SMEM ((64 * QP_STR + 2 * 64 * KV_STR) * 4)

extern __shared__ float att_sm[];

__global__ void __launch_bounds__(128) attn_tc_kernel(
    const float* __restrict__ Q, const float* __restrict__ KV, float* __restrict__ O)
{
    float* sQP = att_sm;                    // 64*68
    float* sK  = sQP + 64 * QP_STR;         // 64*76
    float* sV  = sK  + 64 * KV_STR;         // 64*76

    int tid = threadIdx.x, warp = tid >> 5, lane = tid & 31;
    int g = lane >> 2, t = lane & 3;
    int wm = warp * 16;
    int qt = (int)gridDim.x - 1 - (int)blockIdx.x;   // heavy tiles first
    int h = blockIdx.y, b = blockIdx.z;
    int qrow0 = qt * 64;

    // ---- load Q tile -> smem ----
    #pragma unroll
    for (int it = 0; it < 8; it++) {
        int idx = tid + it * 128;
        int r = idx >> 4, c4 = idx & 15;
        float4 v = *(const float4*)&Q[((size_t)(b * SEQ + qrow0 + r)) * DMODEL + h * DH + c4 * 4];
        *(float4*)&sQP[r * QP_STR + c4 * 4] = v;
    }
    __syncthreads();

    // ---- Q A-fragments in registers (already tf32-rounded) ----
    unsigned qa[8][4];
    #pragma unroll
    for (int ks = 0; ks < 8; ks++) {
        qa[ks][0] = __float_as_uint(sQP[(wm + g)     * QP_STR + ks * 8 + t]);
        qa[ks][1] = __float_as_uint(sQP[(wm + g + 8) * QP_STR + ks * 8 + t]);
        qa[ks][2] = __float_as_uint(sQP[(wm + g)     * QP_STR + ks * 8 + t + 4]);
        qa[ks][3] = __float_as_uint(sQP[(wm + g + 8) * QP_STR + ks * 8 + t + 4]);
    }
    __syncthreads();   // QP buffer now free for P

    float m0 = -INFINITY, m1 = -INFINITY, l0 = 0.f, l1 = 0.f;
    float co[8][4] = {};

    for (int ch = 0; ch <= qt; ch++) {
        // ---- load K/V chunk ----
        #pragma unroll
        for (int it = 0; it < 8; it++) {
            int idx = tid + it * 128;
            int r = idx >> 4, c4 = idx & 15;
            size_t base = ((size_t)(b * SEQ + ch * 64 + r)) * (2 * DMODEL) + h * DH + c4 * 4;
            float4 k4 = *(const float4*)&KV[base];
            float4 v4 = *(const float4*)&KV[base + DMODEL];
            *(float4*)&sK[r * KV_STR + c4 * 4] = k4;
            *(float4*)&sV[r * KV_STR + c4 * 4] = v4;
        }
        __syncthreads();

        // ---- S = Q K^T (log2 domain) ----
        float s[8][4] = {};
        #pragma unroll
        for (int ks = 0; ks < 8; ks++) {
            #pragma unroll
            for (int nf = 0; nf < 8; nf++) {
                unsigned b0 = __float_as_uint(sK[(nf * 8 + g) * KV_STR + ks * 8 + t]);
                unsigned b1 = __float_as_uint(sK[(nf * 8 + g) * KV_STR + ks * 8 + t + 4]);
                mma_tf32(s[nf], qa[ks][0], qa[ks][1], qa[ks][2], qa[ks][3], b0, b1);
            }
        }

        // ---- causal mask (diagonal chunk only) ----
        if (ch == qt) {
            int r0 = wm + g, r1 = wm + g + 8;
            #pragma unroll
            for (int nf = 0; nf < 8; nf++) {
                int col = nf * 8 + 2 * t;
                if (col     > r0) s[nf][0] = -1e30f;
                if (col + 1 > r0) s[nf][1] = -1e30f;
                if (col     > r1) s[nf][2] = -1e30f;
                if (col + 1 > r1) s[nf][3] = -1e30f;
            }
        }

        // ---- online softmax (base-2, quad-lane reductions) ----
        float mx0 = -1e30f, mx1 = -1e30f;
        #pragma unroll
        for (int nf = 0; nf < 8; nf++) {
            mx0 = fmaxf(mx0, fmaxf(s[nf][0], s[nf][1]));
            mx1 = fmaxf(mx1, fmaxf(s[nf][2], s[nf][3]));
        }
        mx0 = fmaxf(mx0, __shfl_xor_sync(0xffffffffu, mx0, 1));
        mx0 = fmaxf(mx0, __shfl_xor_sync(0xffffffffu, mx0, 2));
        mx1 = fmaxf(mx1, __shfl_xor_sync(0xffffffffu, mx1, 1));
        mx1 = fmaxf(mx1, __shfl_xor_sync(0xffffffffu, mx1, 2));
        float nm0 = fmaxf(m0, mx0), nm1 = fmaxf(m1, mx1);
        float sc0 = ex2(m0 - nm0), sc1 = ex2(m1 - nm1);
        m0 = nm0; m1 = nm1;
        float sum0 = 0.f, sum1 = 0.f;
        #pragma unroll
        for (int nf = 0; nf < 8; nf++) {
            s[nf][0] = ex2(s[nf][0] - m0); sum0 += s[nf][0];
            s[nf][1] = ex2(s[nf][1] - m0); sum0 += s[nf][1];
            s[nf][2] = ex2(s[nf][2] - m1); sum1 += s[nf][2];
            s[nf][3] = ex2(s[nf][3] - m1); sum1 += s[nf][3];
        }
        sum0 += __shfl_xor_sync(0xffffffffu, sum0, 1);
        sum0 += __shfl_xor_sync(0xffffffffu, sum0, 2);
        sum1 += __shfl_xor_sync(0xffffffffu, sum1, 1);
        sum1 += __shfl_xor_sync(0xffffffffu, sum1, 2);
        l0 = l0 * sc0 + sum0;
        l1 = l1 * sc1 + sum1;
        #pragma unroll
        for (int nf = 0; nf < 8; nf++) {
            co[nf][0] *= sc0; co[nf][1] *= sc0;
            co[nf][2] *= sc1; co[nf][3] *= sc1;
        }

        // ---- write P (tf32, rna) to this warp's rows of QP buffer ----
        #pragma unroll
        for (int nf = 0; nf < 8; nf++) {
            int cbase = nf * 8 + 2 * t;
            sQP[(wm + g)     * QP_STR + cbase]     = __uint_as_float(f2tf(s[nf][0]));
            sQP[(wm + g)     * QP_STR + cbase + 1] = __uint_as_float(f2tf(s[nf][1]));
            sQP[(wm + g + 8) * QP_STR + cbase]     = __uint_as_float(f2tf(s[nf][2]));
            sQP[(wm + g + 8) * QP_STR + cbase + 1] = __uint_as_float(f2tf(s[nf][3]));
        }
        __syncwarp();

        // ---- O += P V  (V already tf32-rounded; raw bits) ----
        #pragma unroll
        for (int ks = 0; ks < 8; ks++) {
            unsigned pa0 = __float_as_uint(sQP[(wm + g)     * QP_STR + ks * 8 + t]);
            unsigned pa1 = __float_as_uint(sQP[(wm + g + 8) * QP_STR + ks * 8 + t]);
            unsigned pa2 = __float_as_uint(sQP[(wm + g)     * QP_STR + ks * 8 + t + 4]);
            unsigned pa3 = __float_as_uint(sQP[(wm + g + 8) * QP_STR + ks * 8 + t + 4]);
            #pragma unroll
            for (int nf = 0; nf < 8; nf++) {
                unsigned b0 = __float_as_uint(sV[(ks * 8 + t)     * KV_STR + nf * 8 + g]);
                unsigned b1 = __float_as_uint(sV[(ks * 8 + t + 4) * KV_STR + nf * 8 + g]);
                mma_tf32(co[nf], pa0, pa1, pa2, pa3, b0, b1);
            }
        }
        __syncthreads();   // before next chunk overwrites sK/sV
    }

    // ---- epilogue ----
    float inv0 = 1.f / l0, inv1 = 1.f / l1;
    size_t row0 = (size_t)(b * SEQ + qrow0 + wm + g) * DMODEL + h * DH;
    size_t row1 = (size_t)(b * SEQ + qrow0 + wm + g + 8) * DMODEL + h * DH;
    #pragma unroll
    for (int nf = 0; nf < 8; nf++) {
        int cbase = nf * 8 + 2 * t;
        *(float2*)&O[row0 + cbase] = make_float2(co[nf][0] * inv0, co[nf][1] * inv0);
        *(float2*)&O[row1 + cbase] = make_float2(co[nf][2] * inv1, co[nf][3] * inv1);
    }
}

// ---------------- launch ----------------
extern "C" void kernel_launch(void* const* d_in, const int* in_sizes, int n_in,
                              void* d_out, int out_size)
{
    const float* x     = (const float*)d_in[0];
    const float* W_dq  = (const float*)d_in[1];
    const float* W_uq  = (const float*)d_in[2];
    const float* q_g   = (const float*)d_in[3];
    const float* q_b   = (const float*)d_in[4];
    const float* W_dkv = (const float*)d_in[5];
    const float* W_ukv = (const float*)d_in[6];
    const float* kv_g  = (const float*)d_in[7];
    const float* kv_b  = (const float*)d_in[8];
    const float* pq_g  = (const float*)d_in[9];
    const float* pq_b  = (const float*)d_in[10];
    const float* pk_g  = (const float*)d_in[11];
    const float* pk_b  = (const float*)d_in[12];
    const float* wo    = (const float*)d_in[13];
    float* out = (float*)d_out;

    float *xq, *xkv, *tq, *cq, *Qp, *tkv, *ckv, *KV, *attn;
    cudaGetSymbolAddress((void**)&xq,   g_xq);
    cudaGetSymbolAddress((void**)&xkv,  g_xkv);
    cudaGetSymbolAddress((void**)&tq,   g_tq);
    cudaGetSymbolAddress((void**)&cq,   g_cq);
    cudaGetSymbolAddress((void**)&Qp,   g_Q);
    cudaGetSymbolAddress((void**)&tkv,  g_tkv);
    cudaGetSymbolAddress((void**)&ckv,  g_ckv);
    cudaGetSymbolAddress((void**)&KV,   g_KV);
    cudaGetSymbolAddress((void**)&attn, g_attn);

    cudaFuncSetAttribute(attn_tc_kernel, cudaFuncAttributeMaxDynamicSharedMemorySize, ATT_SMEM);

    // 1. fused dual pre-LN (shared mean/var)
    prenorm_kernel<<<MROWS, 256>>>(x, pq_g, pq_b, pk_g, pk_b, xq, xkv);
    // 2-4. Q path (Q stored tf32-rounded, pre-scaled by 0.125*log2e for exp2 softmax)
    gemm_tf32<false, false><<<dim3(QPROJ / GBN, MROWS / GBM), 256>>>(xq, W_dq, tq, QPROJ, DMODEL, 1.f);
    ln_kernel<<<MROWS, 256>>>(tq, q_g, q_b, cq, QPROJ);
    gemm_tf32<false, true><<<dim3(DMODEL / GBN, MROWS / GBM), 256>>>(cq, W_uq, Qp, DMODEL, QPROJ, 0.125f * LOG2E);
    // 5-7. KV path (KV stored tf32-rounded)
    gemm_tf32<false, false><<<dim3(KVPROJ / GBN, MROWS / GBM), 256>>>(xkv, W_dkv, tkv, KVPROJ, DMODEL, 1.f);
    ln_kernel<<<MROWS, 256>>>(tkv, kv_g, kv_b, ckv, KVPROJ);
    gemm_tf32<false, true><<<dim3(2 * DMODEL / GBN, MROWS / GBM), 256>>>(ckv, W_ukv, KV, 2 * DMODEL, KVPROJ, 1.f);
    // 8. tensor-core causal flash attention
    attn_tc_kernel<<<dim3(SEQ / 64, NH, BATCH), 128, ATT_SMEM>>>(Qp, KV, attn);
    // 9. output projection: attn @ wo^T
    gemm_tf32<true, false><<<dim3(DMODEL / GBN, MROWS / GBM), 256>>>(attn, wo, out, DMODEL, DMODEL, 1.f);
}